// round 2
// baseline (speedup 1.0000x reference)
#include <cuda_runtime.h>

// GCN 3-layer: h_l+1 = D^-1/2 (A+I) D^-1/2 (h_l W) + b, relu between.
// Rewrite: ht = (hW)*isq per node;  agg[d] = isq[d] * (sum_{e:d} ht[src] + ht[d])
// -> per-edge work is ONLY gather ht[src] + atomic add into acc[dst].
// NOTE: edge_index arrives as int32 (JAX x64 disabled demotes int64).

#define GN 100000
#define GE 3200000
#define GK 512
#define GC 16

#define TILE_R 256
#define GBLK 64
#define RPT 4
#define KC 16
#define PITCH 20   // floats per smem row (16 data + 4 pad) -> conflict-free LDS.128

// ---------------- scratch (static device globals; no allocation) -------------
__device__ __align__(256) float g_deg[GN];
__device__ __align__(256) float g_isq[GN];
__device__ __align__(256) float g_ht1[GN * GC];
__device__ __align__(256) float g_acc1[GN * GC];
__device__ __align__(256) float g_ht2[GN * GC];
__device__ __align__(256) float g_acc2[GN * GC];
__device__ __align__(256) float g_ht3[GN];
__device__ __align__(256) float g_acc3[GN];
__device__ __align__(256) int   g_src[GE];
__device__ __align__(256) int   g_dst[GE];

// ---------------- f32x2 helpers ----------------------------------------------
__device__ __forceinline__ unsigned long long ffma2(unsigned long long a,
                                                    unsigned long long b,
                                                    unsigned long long c) {
    unsigned long long d;
    asm("fma.rn.f32x2 %0, %1, %2, %3;" : "=l"(d) : "l"(a), "l"(b), "l"(c));
    return d;
}
__device__ __forceinline__ unsigned long long pack2(float a) {
    unsigned long long r;
    unsigned u = __float_as_uint(a);
    asm("mov.b64 %0, {%1, %1};" : "=l"(r) : "r"(u));
    return r;
}

// ---------------- prep kernels -----------------------------------------------
__global__ void k_initdeg(int n) {
    int i = blockIdx.x * blockDim.x + threadIdx.x;
    if (i < n) g_deg[i] = 1.0f;
}

// edge_index is int32: row0 = src[e], row1 = dst[e]
__global__ void k_prep(const int* __restrict__ ei, int e, int n) {
    int i = blockIdx.x * blockDim.x + threadIdx.x;
    if (i >= e) return;
    int s = ei[i];
    int d = ei[e + i];
    // defensive: drop malformed edges instead of crashing
    if ((unsigned)s >= (unsigned)n || (unsigned)d >= (unsigned)n) {
        g_src[i] = 0;
        g_dst[i] = 0;
        return;
    }
    g_src[i] = s;
    g_dst[i] = d;
    atomicAdd(&g_deg[d], 1.0f);
}

__global__ void k_isqrt(int n) {
    int i = blockIdx.x * blockDim.x + threadIdx.x;
    if (i < n) g_isq[i] = rsqrtf(g_deg[i]);
}

// ---------------- GEMM1: ht1 = (x @ W1) * isq ; acc1 = ht1 -------------------
// block = 64 threads, tile = 256 rows, thread = 4 rows (interleaved by 64) x 16 ch
// f32x2 accumulators (8 channel-pairs per row).
__global__ void __launch_bounds__(GBLK) k_gemm1(const float* __restrict__ x,
                                                const float* __restrict__ W1,
                                                int n) {
    __shared__ float sX[TILE_R * PITCH];  // 20 KB
    __shared__ float sW[KC * GC];         // 1 KB (per-chunk W slice)
    int t = threadIdx.x;
    int rb = blockIdx.x * TILE_R;

    unsigned long long acc[RPT][8];
#pragma unroll
    for (int i = 0; i < RPT; i++)
#pragma unroll
        for (int p = 0; p < 8; p++) acc[i][p] = 0ull;

    for (int kb = 0; kb < GK; kb += KC) {
        __syncthreads();
        // stage W chunk [KC][16]
#pragma unroll
        for (int j = 0; j < (KC * GC) / GBLK; j++)
            sW[t + GBLK * j] = W1[(size_t)kb * GC + t + GBLK * j];
        // stage x tile [256 rows][16 k] (4 lanes per row -> 64B/row coalesced)
#pragma unroll
        for (int j = 0; j < 16; j++) {
            int idx = t + GBLK * j;          // 0..1023
            int row = idx >> 2, g = idx & 3;
            int gr = rb + row;
            float4 v = make_float4(0.f, 0.f, 0.f, 0.f);
            if (gr < n) v = *(const float4*)(x + (size_t)gr * GK + kb + 4 * g);
            *(float4*)(sX + row * PITCH + 4 * g) = v;
        }
        __syncthreads();

#pragma unroll
        for (int k4 = 0; k4 < 4; k4++) {
            float4 xv[RPT];
#pragma unroll
            for (int i = 0; i < RPT; i++)
                xv[i] = *(const float4*)(sX + (t + GBLK * i) * PITCH + 4 * k4);
#pragma unroll
            for (int kk = 0; kk < 4; kk++) {
                int klocal = 4 * k4 + kk;
                unsigned long long w2[8];
                const unsigned long long* wr =
                    (const unsigned long long*)(sW + klocal * GC);
#pragma unroll
                for (int p = 0; p < 8; p++) w2[p] = wr[p];
#pragma unroll
                for (int i = 0; i < RPT; i++) {
                    const float* xf = (const float*)&xv[i];
                    unsigned long long x2 = pack2(xf[kk]);
#pragma unroll
                    for (int p = 0; p < 8; p++)
                        acc[i][p] = ffma2(x2, w2[p], acc[i][p]);
                }
            }
        }
    }

    // epilogue: scale by isq, write ht1 and acc1 (self-loop init)
#pragma unroll
    for (int i = 0; i < RPT; i++) {
        int gr = rb + t + GBLK * i;
        if (gr < n) {
            float s = g_isq[gr];
            float o[16];
#pragma unroll
            for (int p = 0; p < 8; p++) {
                unsigned lo, hi;
                asm("mov.b64 {%0,%1}, %2;" : "=r"(lo), "=r"(hi) : "l"(acc[i][p]));
                o[2 * p]     = __uint_as_float(lo) * s;
                o[2 * p + 1] = __uint_as_float(hi) * s;
            }
            float4* hp = (float4*)(g_ht1 + (size_t)gr * GC);
            float4* ap = (float4*)(g_acc1 + (size_t)gr * GC);
#pragma unroll
            for (int q = 0; q < 4; q++) {
                float4 v = ((const float4*)o)[q];
                hp[q] = v;
                ap[q] = v;
            }
        }
    }
}

// ---------------- edge scatter, 16 channels (4 lanes per edge) ---------------
__global__ void __launch_bounds__(256) k_scatter16(int phase2, int e) {
    int tid = blockIdx.x * blockDim.x + threadIdx.x;
    int ed = tid >> 2;
    if (ed >= e) return;
    int q = tid & 3;
    const float4* ht = (const float4*)(phase2 ? g_ht2 : g_ht1);
    float* acc = phase2 ? g_acc2 : g_acc1;
    int s = g_src[ed];
    int d = g_dst[ed];
    float4 v = __ldg(ht + (size_t)s * 4 + q);
    float* p = acc + (size_t)d * GC + q * 4;
    asm volatile("red.global.add.v4.f32 [%0], {%1,%2,%3,%4};"
                 :: "l"(p), "f"(v.x), "f"(v.y), "f"(v.z), "f"(v.w)
                 : "memory");
}

// ---------------- layer2: z=relu(isq*acc1+b1); ht2=(z@W2)*isq; acc2=ht2 ------
__global__ void __launch_bounds__(256) k_layer2(const float* __restrict__ W2,
                                                const float* __restrict__ b1,
                                                int n) {
    __shared__ float sW[GC * GC];
    __shared__ float sb[GC];
    if (threadIdx.x < GC * GC) sW[threadIdx.x] = W2[threadIdx.x];
    if (threadIdx.x < GC) sb[threadIdx.x] = b1[threadIdx.x];
    __syncthreads();
    int i = blockIdx.x * blockDim.x + threadIdx.x;
    if (i >= n) return;
    float s = g_isq[i];
    float z[GC];
    const float4* ar = (const float4*)(g_acc1) + (size_t)i * 4;
#pragma unroll
    for (int q = 0; q < 4; q++) {
        float4 v = ar[q];
        z[4 * q + 0] = fmaxf(s * v.x + sb[4 * q + 0], 0.f);
        z[4 * q + 1] = fmaxf(s * v.y + sb[4 * q + 1], 0.f);
        z[4 * q + 2] = fmaxf(s * v.z + sb[4 * q + 2], 0.f);
        z[4 * q + 3] = fmaxf(s * v.w + sb[4 * q + 3], 0.f);
    }
    float acc[GC];
#pragma unroll
    for (int c = 0; c < GC; c++) acc[c] = 0.f;
#pragma unroll
    for (int k = 0; k < GC; k++) {
        float zk = z[k];
#pragma unroll
        for (int c = 0; c < GC; c++) acc[c] = fmaf(zk, sW[k * GC + c], acc[c]);
    }
    float4* hp = (float4*)(g_ht2 + (size_t)i * GC);
    float4* ap = (float4*)(g_acc2 + (size_t)i * GC);
#pragma unroll
    for (int q = 0; q < 4; q++) {
        float4 v = make_float4(acc[4 * q] * s, acc[4 * q + 1] * s,
                               acc[4 * q + 2] * s, acc[4 * q + 3] * s);
        hp[q] = v;
        ap[q] = v;
    }
}

// ---------------- layer3: z=relu(isq*acc2+b2); ht3=(z.W3)*isq; acc3=ht3 ------
__global__ void __launch_bounds__(256) k_layer3(const float* __restrict__ W3,
                                                const float* __restrict__ b2,
                                                int n) {
    __shared__ float sW[GC];
    __shared__ float sb[GC];
    if (threadIdx.x < GC) {
        sW[threadIdx.x] = W3[threadIdx.x];
        sb[threadIdx.x] = b2[threadIdx.x];
    }
    __syncthreads();
    int i = blockIdx.x * blockDim.x + threadIdx.x;
    if (i >= n) return;
    float s = g_isq[i];
    const float4* ar = (const float4*)(g_acc2) + (size_t)i * 4;
    float h3 = 0.f;
#pragma unroll
    for (int q = 0; q < 4; q++) {
        float4 v = ar[q];
        h3 = fmaf(fmaxf(s * v.x + sb[4 * q + 0], 0.f), sW[4 * q + 0], h3);
        h3 = fmaf(fmaxf(s * v.y + sb[4 * q + 1], 0.f), sW[4 * q + 1], h3);
        h3 = fmaf(fmaxf(s * v.z + sb[4 * q + 2], 0.f), sW[4 * q + 2], h3);
        h3 = fmaf(fmaxf(s * v.w + sb[4 * q + 3], 0.f), sW[4 * q + 3], h3);
    }
    float v = h3 * s;
    g_ht3[i] = v;
    g_acc3[i] = v;
}

// ---------------- scalar edge scatter for layer3 -----------------------------
__global__ void __launch_bounds__(256) k_scatter1(int e) {
    int i = blockIdx.x * blockDim.x + threadIdx.x;
    if (i >= e) return;
    atomicAdd(&g_acc3[g_dst[i]], g_ht3[g_src[i]]);
}

// ---------------- final: out = isq*acc3 + b3 ---------------------------------
__global__ void __launch_bounds__(256) k_final(const float* __restrict__ b3,
                                               float* __restrict__ out, int n) {
    int i = blockIdx.x * blockDim.x + threadIdx.x;
    if (i < n) out[i] = g_isq[i] * g_acc3[i] + __ldg(b3);
}

// ---------------- launch -----------------------------------------------------
extern "C" void kernel_launch(void* const* d_in, const int* in_sizes, int n_in,
                              void* d_out, int out_size) {
    const float* x  = (const float*)d_in[0];
    const int*   ei = (const int*)d_in[1];   // int32 edge_index [2, E]
    const float* W1 = (const float*)d_in[2];
    const float* b1 = (const float*)d_in[3];
    const float* W2 = (const float*)d_in[4];
    const float* b2 = (const float*)d_in[5];
    const float* W3 = (const float*)d_in[6];
    const float* b3 = (const float*)d_in[7];
    float* out = (float*)d_out;

    int n = in_sizes[0] / GK;
    int e = in_sizes[1] / 2;
    if (n > GN) n = GN;
    if (e > GE) e = GE;

    int nb = (n + 255) / 256;
    int eb = (e + 255) / 256;
    int e4b = (4 * e + 255) / 256;

    k_initdeg<<<nb, 256>>>(n);
    k_prep<<<eb, 256>>>(ei, e, n);
    k_isqrt<<<nb, 256>>>(n);
    k_gemm1<<<(n + TILE_R - 1) / TILE_R, GBLK>>>(x, W1, n);
    k_scatter16<<<e4b, 256>>>(0, e);
    k_layer2<<<nb, 256>>>(W2, b1, n);
    k_scatter16<<<e4b, 256>>>(1, e);
    k_layer3<<<nb, 256>>>(W3, b2, n);
    k_scatter1<<<eb, 256>>>(e);
    k_final<<<nb, 256>>>(b3, out, n);
}